// round 14
// baseline (speedup 1.0000x reference)
#include <cuda_runtime.h>
#include <cuda_fp16.h>
#include <cstdint>

#define N_NODES 50000
#define E_EDGES 800000

// ---------------- static scratch (no allocs allowed) ----------------
__device__ __half g_t256h[N_NODES * 256];
__device__ __half g_ha[N_NODES * 512];
__device__ __half g_hb[N_NODES * 512];
#define W_TOTAL 983040
__device__ __half g_wh[W_TOTAL];
// CSR scratch
__device__ int g_deg[N_NODES];
__device__ int g_off[N_NODES];
__device__ int g_cursor[N_NODES];
__device__ int g_csr_src[E_EDGES];
__device__ int g_base;
__device__ int g_is64;

// weight pack offsets (elements)
#define OFF_S1  0
#define OFF_S2  32768
#define OFF_S3  294912
#define OFF_S4  557056
#define OFF_CAT 819200
#define OFF_M2  950272
#define OFF_L2  966656

__device__ __forceinline__ uint32_t smem_u32(const void* p) {
    uint32_t a;
    asm("{ .reg .u64 t; cvta.to.shared.u64 t, %1; cvt.u32.u64 %0, t; }" : "=r"(a) : "l"(p));
    return a;
}
#define SW128(o) ((o) ^ (((o) >> 3) & 0x70))

// ---------------- edge-index helpers ----------------
__global__ void detect_idx_kernel(const unsigned long long* ei) {
    if (blockIdx.x == 0 && threadIdx.x == 0) {
        int ok = 1;
        #pragma unroll
        for (int i = 0; i < 16; i++)
            if (ei[i] >= (unsigned long long)N_NODES) ok = 0;
        g_is64 = ok;
        g_base = 0;
    }
}
__device__ __forceinline__ void load_edge(const void* ei_raw, int e, int& s, int& d) {
    if (g_is64) {
        const long long* p = (const long long*)ei_raw;
        s = (int)__ldg(p + e); d = (int)__ldg(p + E_EDGES + e);
    } else {
        const int* p = (const int*)ei_raw;
        s = __ldg(p + e); d = __ldg(p + E_EDGES + e);
    }
}

// ---------------- CSR build ----------------
__global__ void hist_kernel(const void* ei, int* deg) {
    int t = blockIdx.x * blockDim.x + threadIdx.x;
    if (t >= E_EDGES / 2) return;
    if (g_is64) {
        const longlong2* p = (const longlong2*)((const long long*)ei + E_EDGES);
        longlong2 v = __ldg(p + t);
        atomicAdd(&deg[(int)v.x], 1);
        atomicAdd(&deg[(int)v.y], 1);
    } else {
        const int2* p = (const int2*)((const int*)ei + E_EDGES);
        int2 v = __ldg(p + t);
        atomicAdd(&deg[v.x], 1);
        atomicAdd(&deg[v.y], 1);
    }
}
#define SCAN_B 1024
__global__ void scan_fused_kernel(const int* __restrict__ deg, int* __restrict__ off,
                                  int* __restrict__ cursor, int* __restrict__ gbase) {
    __shared__ int sh[SCAN_B];
    __shared__ int base;
    int tid = threadIdx.x;
    int i = blockIdx.x * SCAN_B + tid;
    int v = (i < N_NODES) ? deg[i] : 0;
    sh[tid] = v;
    __syncthreads();
    for (int ofs = 1; ofs < SCAN_B; ofs <<= 1) {
        int t = (tid >= ofs) ? sh[tid - ofs] : 0;
        __syncthreads();
        sh[tid] += t;
        __syncthreads();
    }
    if (tid == SCAN_B - 1) base = atomicAdd(gbase, sh[tid]);
    __syncthreads();
    if (i < N_NODES) {
        int o = base + sh[tid] - v;
        off[i] = o;
        cursor[i] = o;
    }
}
__global__ void csr_fill_kernel(const void* ei, int* cursor, int* csr_src) {
    int e = blockIdx.x * blockDim.x + threadIdx.x;
    if (e >= E_EDGES) return;
    int s, d; load_edge(ei, e, s, d);
    int pos = atomicAdd(&cursor[d], 1);
    csr_src[pos] = s;
}

// ---------------- fused aggregations ----------------
__global__ __launch_bounds__(256) void agg64_kernel(
    const float* __restrict__ x, const int* __restrict__ off, const int* __restrict__ deg,
    const int* __restrict__ csr, __half* __restrict__ ha)
{
    int w = (blockIdx.x * blockDim.x + threadIdx.x) >> 5;
    int lane = threadIdx.x & 31;
    if (w >= N_NODES) return;
    float2 acc0 = ((const float2*)(x + (size_t)w * 64))[lane];
    float2 acc1 = make_float2(0.f, 0.f);
    int o = off[w], dg = deg[w];
    int k = 0;
    for (; k + 2 <= dg; k += 2) {
        int s0 = __ldg(csr + o + k);
        int s1 = __ldg(csr + o + k + 1);
        float2 v0 = __ldg((const float2*)(x + (size_t)s0 * 64) + lane);
        float2 v1 = __ldg((const float2*)(x + (size_t)s1 * 64) + lane);
        acc0.x += v0.x; acc0.y += v0.y;
        acc1.x += v1.x; acc1.y += v1.y;
    }
    if (k < dg) {
        int s0 = __ldg(csr + o + k);
        float2 v0 = __ldg((const float2*)(x + (size_t)s0 * 64) + lane);
        acc0.x += v0.x; acc0.y += v0.y;
    }
    acc0.x += acc1.x; acc0.y += acc1.y;
    ((__half2*)(ha + (size_t)w * 64))[lane] = __floats2half2_rn(acc0.x, acc0.y);
}

__device__ __forceinline__ void h8_add(float* acc, uint4 v) {
    const __half2* p = (const __half2*)&v;
    #pragma unroll
    for (int i = 0; i < 4; i++) {
        float2 f = __half22float2(p[i]);
        acc[2 * i] += f.x; acc[2 * i + 1] += f.y;
    }
}

__global__ __launch_bounds__(256) void agg256_heads_kernel(
    const __half* __restrict__ t256, const int* __restrict__ off, const int* __restrict__ deg,
    const int* __restrict__ csr, const float* __restrict__ bm1, const float* __restrict__ bl1,
    __half* __restrict__ hh)
{
    int w = (blockIdx.x * blockDim.x + threadIdx.x) >> 5;
    int lane = threadIdx.x & 31;
    if (w >= N_NODES) return;

    float acc0[8] = {}, acc1[8] = {};
    h8_add(acc0, __ldg((const uint4*)(t256 + (size_t)w * 256) + lane));

    int o = off[w], dg = deg[w];
    int k = 0;
    for (; k + 2 <= dg; k += 2) {
        int s0 = __ldg(csr + o + k);
        int s1 = __ldg(csr + o + k + 1);
        uint4 v0 = __ldg((const uint4*)(t256 + (size_t)s0 * 256) + lane);
        uint4 v1 = __ldg((const uint4*)(t256 + (size_t)s1 * 256) + lane);
        h8_add(acc0, v0);
        h8_add(acc1, v1);
    }
    if (k < dg) {
        int s0 = __ldg(csr + o + k);
        h8_add(acc0, __ldg((const uint4*)(t256 + (size_t)s0 * 256) + lane));
    }
    #pragma unroll
    for (int i = 0; i < 8; i++) acc0[i] += acc1[i];

    const float* bias = (lane < 16) ? (bm1 + lane * 8) : (bl1 + (lane - 16) * 8);
    float4 bv0 = __ldg((const float4*)bias);
    float4 bv1 = __ldg((const float4*)bias + 1);
    float bb[8] = {bv0.x, bv0.y, bv0.z, bv0.w, bv1.x, bv1.y, bv1.z, bv1.w};

    uint4 pk;
    __half2* q = (__half2*)&pk;
    #pragma unroll
    for (int i = 0; i < 4; i++) {
        float v0 = fmaxf(acc0[2 * i]     + bb[2 * i],     0.f);
        float v1 = fmaxf(acc0[2 * i + 1] + bb[2 * i + 1], 0.f);
        q[i] = __floats2half2_rn(v0, v1);
    }
    size_t dst = (lane < 16)
        ? ((size_t)w * 128 + lane * 8)
        : ((size_t)N_NODES * 128 + (size_t)w * 128 + (lane - 16) * 8);
    *(uint4*)(hh + dst) = pk;
}

// ---------------- batched weight convert: fp32 -> fp16 ----------------
struct WSrc { const float2* p[8]; };
__global__ void split_weights_kernel(WSrc ws, __half2* __restrict__ hi) {
    int i = blockIdx.x * blockDim.x + threadIdx.x;
    const int ends[8]   = {16384, 147456, 278528, 409600, 442368, 475136, 483328, 491520};
    const int starts[8] = {0, 16384, 147456, 278528, 409600, 442368, 475136, 483328};
    if (i >= 491520) return;
    int seg = 0;
    #pragma unroll
    for (int s = 0; s < 7; s++) if (i >= ends[s]) seg = s + 1;
    float2 v = ws.p[seg][i - starts[seg]];
    hi[i] = __halves2half2(__float2half(v.x), __float2half(v.y));
}

// ---------------- mma.sync fp16 GEMM, 64-row tiles (wave-tail reduction) ----------------
// C[M,Nn] = act(A[M,K] @ W[Nn,K]^T + bias); A, W fp16, fp32 accum.
// CTA tile 64x128: 8 warps as 2(m) x 4(n), each 32x32 warp tile.
// K in 64-elem SW128 chunks, cp.async double buffer (2 x 24KB smem -> 2 CTA/SM).
// Finer M granularity: ~10.6 waves instead of 5.3 -> tail idle 12% -> 4%.
#define GT 256
#define SMEM_GEMM 49152
#define BUFB 24576
#define W_OFFS 8192      // W tile at +8KB within each buffer (A tile is 64*128B)

#define LDSM4(r0, r1, r2, r3, a) \
    asm volatile("ldmatrix.sync.aligned.m8n8.x4.shared.b16 {%0,%1,%2,%3}, [%4];" \
                 : "=r"(r0), "=r"(r1), "=r"(r2), "=r"(r3) : "r"(a))

#define HMMA(c, a0, a1, a2, a3, b0, b1) \
    asm volatile("mma.sync.aligned.m16n8k16.row.col.f32.f16.f16.f32 " \
                 "{%0,%1,%2,%3}, {%4,%5,%6,%7}, {%8,%9}, {%0,%1,%2,%3};" \
                 : "+f"((c)[0]), "+f"((c)[1]), "+f"((c)[2]), "+f"((c)[3]) \
                 : "r"(a0), "r"(a1), "r"(a2), "r"(a3), "r"(b0), "r"(b1))

__device__ __forceinline__ void cp16(uint32_t saddr, const void* gptr, uint32_t sz) {
    asm volatile("cp.async.cg.shared.global [%0], [%1], 16, %2;"
                 :: "r"(saddr), "l"(gptr), "r"(sz) : "memory");
}
#define CP_COMMIT() asm volatile("cp.async.commit_group;" ::: "memory")
#define CP_WAIT(n)  asm volatile("cp.async.wait_group %0;" :: "n"(n) : "memory")

template <int ACT, bool EMITF, bool EMITH, bool HASB, bool ZSEL>
__global__ __launch_bounds__(GT, 2)
void gemm_tc(const __half* __restrict__ A, const __half* __restrict__ A2, int lda,
             const __half* __restrict__ W, const __half* __restrict__ W2,
             const float* __restrict__ bias, const float* __restrict__ bias2,
             float* __restrict__ C, float* __restrict__ C2, int ldc,
             __half* __restrict__ Ch, int ldch,
             int M, int K)
{
    extern __shared__ char smem[];
    const uint32_t sb = smem_u32(smem);

    if (ZSEL && blockIdx.z) { A = A2; W = W2; bias = bias2; C = C2; }

    const int tid = threadIdx.x;
    const int wid = tid >> 5;
    const int lane = tid & 31;
    const int m0 = blockIdx.y * 64;
    const int n0 = blockIdx.x * 128;
    const int wm = (wid & 1) * 32;       // 2 m-bands of 32
    const int wn = (wid >> 1) * 32;      // 4 n-bands of 32

    float acc[2][4][4] = {};

    // staging: A = 64 rows x 8 groups(16B) = 512 groups (2/thread);
    //          W = 128 rows x 8 groups      = 1024 groups (4/thread)
    const int arow_s = tid >> 2;             // 0..63  (A: 4 threads/row -> 2 groups each)
    const int ag_s   = (tid & 3) * 2;        // group pair start
    const int wrow_s = tid >> 3, wg_s = tid & 7;

    auto stage = [&](int buf, int k0) {
        const uint32_t tb = sb + buf * BUFB;
        // A tile: thread covers groups (arow_s, ag_s) and (arow_s, ag_s+1)
        {
            const int ar = m0 + arow_s;
            const int ok = (ar < M);
            const size_t ao = (size_t)(ok ? ar : 0) * lda + k0 + ag_s * 8;
            const uint32_t so0 = SW128((uint32_t)(arow_s * 128 + ag_s * 16));
            const uint32_t so1 = SW128((uint32_t)(arow_s * 128 + (ag_s + 1) * 16));
            cp16(tb + so0, A + ao,     ok ? 16 : 0);
            cp16(tb + so1, A + ao + 8, ok ? 16 : 0);
        }
        // W tile: 4 chunks of 32 rows
        #pragma unroll
        for (int t = 0; t < 4; t++) {
            const int row = wrow_s + t * 32;
            const uint32_t so = SW128((uint32_t)(row * 128 + wg_s * 16));
            const size_t wo = (size_t)(n0 + row) * K + k0 + wg_s * 8;
            cp16(tb + W_OFFS + so, W + wo, 16);
        }
        CP_COMMIT();
    };

    const int o = lane >> 3, r = lane & 7;
    int aRow[2];
    #pragma unroll
    for (int i = 0; i < 2; i++) aRow[i] = (wm + 16 * i + (o & 1) * 8 + r) * 128 + (o >> 1) * 16;
    int bRow[2];
    #pragma unroll
    for (int p = 0; p < 2; p++) bRow[p] = (wn + p * 16 + (o >> 1) * 8 + r) * 128 + (o & 1) * 16;

    const int nchunks = K >> 6;
    stage(0, 0);
    for (int c = 0; c < nchunks; c++) {
        if (c + 1 < nchunks) stage((c + 1) & 1, (c + 1) << 6);
        if (c + 1 < nchunks) { CP_WAIT(1); } else { CP_WAIT(0); }
        __syncthreads();

        const uint32_t tb = sb + (c & 1) * BUFB;
        #pragma unroll
        for (int ks = 0; ks < 4; ks++) {
            const int kb = ks * 32;
            uint32_t af[2][4], wf[2][4];
            #pragma unroll
            for (int i = 0; i < 2; i++) {
                const uint32_t ad = SW128((uint32_t)(aRow[i] + kb));
                LDSM4(af[i][0], af[i][1], af[i][2], af[i][3], tb + ad);
            }
            #pragma unroll
            for (int p = 0; p < 2; p++) {
                const uint32_t bd = SW128((uint32_t)(bRow[p] + kb));
                LDSM4(wf[p][0], wf[p][1], wf[p][2], wf[p][3], tb + W_OFFS + bd);
            }
            #pragma unroll
            for (int i = 0; i < 2; i++) {
                #pragma unroll
                for (int j = 0; j < 4; j++) {
                    HMMA(acc[i][j], af[i][0], af[i][1], af[i][2], af[i][3],
                         wf[j >> 1][(j & 1) * 2], wf[j >> 1][(j & 1) * 2 + 1]);
                }
            }
        }
        __syncthreads();
    }

    const int gid = lane >> 2, tig = lane & 3;
    #pragma unroll
    for (int i = 0; i < 2; i++) {
        #pragma unroll
        for (int h = 0; h < 2; h++) {
            const int row = m0 + wm + 16 * i + 8 * h + gid;
            if (row >= M) continue;
            #pragma unroll
            for (int j = 0; j < 4; j++) {
                const int col = n0 + wn + 8 * j + 2 * tig;
                float v0 = acc[i][j][2 * h], v1 = acc[i][j][2 * h + 1];
                if (HASB) { v0 += __ldg(bias + col); v1 += __ldg(bias + col + 1); }
                if (ACT == 1) { v0 = (v0 > 0.f) ? v0 : 0.1f * v0; v1 = (v1 > 0.f) ? v1 : 0.1f * v1; }
                if (ACT == 2) { v0 = fmaxf(v0, 0.f); v1 = fmaxf(v1, 0.f); }
                if (EMITF) {
                    *(float2*)&C[(size_t)row * ldc + col] = make_float2(v0, v1);
                }
                if (EMITH) {
                    *(__half2*)&Ch[(size_t)row * ldch + col] = __floats2half2_rn(v0, v1);
                }
            }
        }
    }
}

// ---------------- launch ----------------
extern "C" void kernel_launch(void* const* d_in, const int* in_sizes, int n_in,
                              void* d_out, int out_size) {
    const float* x    = (const float*)d_in[0];
    const void*  ei   = d_in[1];
    const float* W_s1 = (const float*)d_in[2];
    const float* b_s1 = (const float*)d_in[3];
    const float* W_s2 = (const float*)d_in[4];
    const float* b_s2 = (const float*)d_in[5];
    const float* W_s3 = (const float*)d_in[6];
    const float* b_s3 = (const float*)d_in[7];
    const float* W_s4 = (const float*)d_in[8];
    const float* b_s4 = (const float*)d_in[9];
    const float* W_m1 = (const float*)d_in[10];
    const float* b_m1 = (const float*)d_in[11];
    const float* W_m2 = (const float*)d_in[12];
    const float* b_m2 = (const float*)d_in[13];
    const float* W_l1 = (const float*)d_in[14];
    const float* b_l1 = (const float*)d_in[15];
    const float* W_l2 = (const float*)d_in[16];
    const float* b_l2 = (const float*)d_in[17];
    float* out = (float*)d_out;

    __half *t256h, *ha, *hb, *wh;
    int *deg, *off, *cursor, *csr, *gbase;
    cudaGetSymbolAddress((void**)&t256h, g_t256h);
    cudaGetSymbolAddress((void**)&ha, g_ha);
    cudaGetSymbolAddress((void**)&hb, g_hb);
    cudaGetSymbolAddress((void**)&wh, g_wh);
    cudaGetSymbolAddress((void**)&deg, g_deg);
    cudaGetSymbolAddress((void**)&off, g_off);
    cudaGetSymbolAddress((void**)&cursor, g_cursor);
    cudaGetSymbolAddress((void**)&csr, g_csr_src);
    cudaGetSymbolAddress((void**)&gbase, g_base);

    static bool init_done = false;
    static cudaStream_t s_side = nullptr;
    static cudaEvent_t ev_fork = nullptr, ev_join = nullptr;
    if (!init_done) {
        cudaFuncSetAttribute(gemm_tc<1, false, true,  true,  false>, cudaFuncAttributeMaxDynamicSharedMemorySize, SMEM_GEMM);
        cudaFuncSetAttribute(gemm_tc<2, false, true,  true,  false>, cudaFuncAttributeMaxDynamicSharedMemorySize, SMEM_GEMM);
        cudaFuncSetAttribute(gemm_tc<0, false, true,  false, false>, cudaFuncAttributeMaxDynamicSharedMemorySize, SMEM_GEMM);
        cudaFuncSetAttribute(gemm_tc<0, true,  false, true,  true >, cudaFuncAttributeMaxDynamicSharedMemorySize, SMEM_GEMM);
        cudaStreamCreateWithFlags(&s_side, cudaStreamNonBlocking);
        cudaEventCreateWithFlags(&ev_fork, cudaEventDisableTiming);
        cudaEventCreateWithFlags(&ev_join, cudaEventDisableTiming);
        init_done = true;
    }

    const int M = N_NODES;
    const int MT = (M + 63) / 64;        // 782 M-tiles
    const dim3 blk(GT);
    const dim3 g512(4, MT);
    const dim3 g256(2, MT);
    const dim3 gheads(1, MT, 2);
    const int SCAN_NB = (N_NODES + SCAN_B - 1) / SCAN_B;

    // ---- fork: weight convert on side stream, overlapped with CSR build ----
    cudaEventRecord(ev_fork, 0);
    cudaStreamWaitEvent(s_side, ev_fork, 0);
    {
        WSrc ws;
        ws.p[0] = (const float2*)W_s1;
        ws.p[1] = (const float2*)W_s2;
        ws.p[2] = (const float2*)W_s3;
        ws.p[3] = (const float2*)W_s4;
        ws.p[4] = (const float2*)W_m1;
        ws.p[5] = (const float2*)W_l1;
        ws.p[6] = (const float2*)W_m2;
        ws.p[7] = (const float2*)W_l2;
        split_weights_kernel<<<(491520 + 255) / 256, 256, 0, s_side>>>(ws, (__half2*)wh);
    }
    cudaEventRecord(ev_join, s_side);

    // ---- main stream: CSR build ----
    detect_idx_kernel<<<1, 32>>>((const unsigned long long*)ei);
    cudaMemsetAsync(deg, 0, N_NODES * sizeof(int), 0);
    hist_kernel<<<(E_EDGES / 2 + 255) / 256, 256>>>(ei, deg);
    scan_fused_kernel<<<SCAN_NB, SCAN_B>>>(deg, off, cursor, gbase);
    csr_fill_kernel<<<(E_EDGES + 255) / 256, 256>>>(ei, cursor, csr);

    // ---- agg0 = (I+A)x -> fp16 ----
    agg64_kernel<<<(N_NODES * 32 + 255) / 256, 256>>>(x, off, deg, csr, ha);

    // ---- join: weights ready before s1 ----
    cudaStreamWaitEvent(0, ev_join, 0);

    // ---- shared MLP, fp16 activations chained through epilogues ----
    gemm_tc<1, false, true, true, false><<<g512, blk, SMEM_GEMM>>>(ha, nullptr, 64,  wh + OFF_S1, nullptr, b_s1, nullptr, nullptr, nullptr, 0, hb, 512, M, 64);
    gemm_tc<1, false, true, true, false><<<g512, blk, SMEM_GEMM>>>(hb, nullptr, 512, wh + OFF_S2, nullptr, b_s2, nullptr, nullptr, nullptr, 0, ha, 512, M, 512);
    gemm_tc<1, false, true, true, false><<<g512, blk, SMEM_GEMM>>>(ha, nullptr, 512, wh + OFF_S3, nullptr, b_s3, nullptr, nullptr, nullptr, 0, hb, 512, M, 512);
    gemm_tc<2, false, true, true, false><<<g512, blk, SMEM_GEMM>>>(hb, nullptr, 512, wh + OFF_S4, nullptr, b_s4, nullptr, nullptr, nullptr, 0, ha, 512, M, 512);

    // ---- t256 = h @ [W_m1; W_l1]^T, emitted directly as fp16 ----
    gemm_tc<0, false, true, false, false><<<g256, blk, SMEM_GEMM>>>(ha, nullptr, 512, wh + OFF_CAT, nullptr, nullptr, nullptr, nullptr, nullptr, 0, t256h, 256, M, 512);

    // ---- agg(256) over fp16 t256 + both head prologues fused ----
    agg256_heads_kernel<<<(N_NODES * 32 + 255) / 256, 256>>>(t256h, off, deg, csr, b_m1, b_l1, hb);

    // ---- both heads in ONE launch (blockIdx.z selects head) ----
    gemm_tc<0, true, false, true, true><<<gheads, blk, SMEM_GEMM>>>(
        hb, hb + (size_t)N_NODES * 128, 128,
        wh + OFF_M2, wh + OFF_L2,
        b_m2, b_l2,
        out, out + (size_t)N_NODES * 128, 128,
        nullptr, 0, M, 128);

    (void)in_sizes; (void)n_in; (void)out_size;
}

// round 17
// speedup vs baseline: 1.1168x; 1.1168x over previous
#include <cuda_runtime.h>
#include <cuda_fp16.h>
#include <cstdint>

#define N_NODES 50000
#define E_EDGES 800000

// ---------------- static scratch (no allocs allowed) ----------------
__device__ __half g_t256h[N_NODES * 256];
__device__ __half g_ha[N_NODES * 512];
__device__ __half g_hb[N_NODES * 512];
#define W_TOTAL 983040
__device__ __half g_wh[W_TOTAL];
// CSR scratch
__device__ int g_deg[N_NODES];
__device__ int g_off[N_NODES];
__device__ int g_cursor[N_NODES];
__device__ int g_csr_src[E_EDGES];
__device__ int g_base;
__device__ int g_is64;

// weight pack offsets (elements)
#define OFF_S1  0
#define OFF_S2  32768
#define OFF_S3  294912
#define OFF_S4  557056
#define OFF_CAT 819200
#define OFF_M2  950272
#define OFF_L2  966656

__device__ __forceinline__ uint32_t smem_u32(const void* p) {
    uint32_t a;
    asm("{ .reg .u64 t; cvta.to.shared.u64 t, %1; cvt.u32.u64 %0, t; }" : "=r"(a) : "l"(p));
    return a;
}
#define SW128(o) ((o) ^ (((o) >> 3) & 0x70))

// ---------------- edge-index helpers ----------------
__global__ void detect_idx_kernel(const unsigned long long* ei) {
    if (blockIdx.x == 0 && threadIdx.x == 0) {
        int ok = 1;
        #pragma unroll
        for (int i = 0; i < 16; i++)
            if (ei[i] >= (unsigned long long)N_NODES) ok = 0;
        g_is64 = ok;
        g_base = 0;
    }
}
__device__ __forceinline__ void load_edge(const void* ei_raw, int e, int& s, int& d) {
    if (g_is64) {
        const long long* p = (const long long*)ei_raw;
        s = (int)__ldg(p + e); d = (int)__ldg(p + E_EDGES + e);
    } else {
        const int* p = (const int*)ei_raw;
        s = __ldg(p + e); d = __ldg(p + E_EDGES + e);
    }
}

// ---------------- CSR build ----------------
// hist: dst-only, two edges per thread (coalesced paired loads, independent atomics)
__global__ void hist_kernel(const void* ei, int* deg) {
    int t = blockIdx.x * blockDim.x + threadIdx.x;
    if (t >= E_EDGES / 2) return;
    if (g_is64) {
        const longlong2* p = (const longlong2*)((const long long*)ei + E_EDGES);
        longlong2 v = __ldg(p + t);
        atomicAdd(&deg[(int)v.x], 1);
        atomicAdd(&deg[(int)v.y], 1);
    } else {
        const int2* p = (const int2*)((const int*)ei + E_EDGES);
        int2 v = __ldg(p + t);
        atomicAdd(&deg[v.x], 1);
        atomicAdd(&deg[v.y], 1);
    }
}
// fused scan: block-local prefix + atomic region claim (segment order arbitrary;
// only per-node contiguity matters for the gather kernels).
#define SCAN_B 1024
__global__ void scan_fused_kernel(const int* __restrict__ deg, int* __restrict__ off,
                                  int* __restrict__ cursor, int* __restrict__ gbase) {
    __shared__ int sh[SCAN_B];
    __shared__ int base;
    int tid = threadIdx.x;
    int i = blockIdx.x * SCAN_B + tid;
    int v = (i < N_NODES) ? deg[i] : 0;
    sh[tid] = v;
    __syncthreads();
    for (int ofs = 1; ofs < SCAN_B; ofs <<= 1) {
        int t = (tid >= ofs) ? sh[tid - ofs] : 0;
        __syncthreads();
        sh[tid] += t;
        __syncthreads();
    }
    if (tid == SCAN_B - 1) base = atomicAdd(gbase, sh[tid]);
    __syncthreads();
    if (i < N_NODES) {
        int o = base + sh[tid] - v;
        off[i] = o;
        cursor[i] = o;
    }
}
// fill: one edge per thread (independent atomic per thread)
__global__ void csr_fill_kernel(const void* ei, int* cursor, int* csr_src) {
    int e = blockIdx.x * blockDim.x + threadIdx.x;
    if (e >= E_EDGES) return;
    int s, d; load_edge(ei, e, s, d);
    int pos = atomicAdd(&cursor[d], 1);
    csr_src[pos] = s;
}

// ---------------- fused aggregations ----------------
// agg64: out = fp16(x[n] + sum_{s in N(n)} x[s]) ; one warp per node, 2 cols/lane
__global__ __launch_bounds__(256) void agg64_kernel(
    const float* __restrict__ x, const int* __restrict__ off, const int* __restrict__ deg,
    const int* __restrict__ csr, __half* __restrict__ ha)
{
    int w = (blockIdx.x * blockDim.x + threadIdx.x) >> 5;
    int lane = threadIdx.x & 31;
    if (w >= N_NODES) return;
    float2 acc0 = ((const float2*)(x + (size_t)w * 64))[lane];
    float2 acc1 = make_float2(0.f, 0.f);
    int o = off[w], dg = deg[w];
    int k = 0;
    for (; k + 2 <= dg; k += 2) {
        int s0 = __ldg(csr + o + k);
        int s1 = __ldg(csr + o + k + 1);
        float2 v0 = __ldg((const float2*)(x + (size_t)s0 * 64) + lane);
        float2 v1 = __ldg((const float2*)(x + (size_t)s1 * 64) + lane);
        acc0.x += v0.x; acc0.y += v0.y;
        acc1.x += v1.x; acc1.y += v1.y;
    }
    if (k < dg) {
        int s0 = __ldg(csr + o + k);
        float2 v0 = __ldg((const float2*)(x + (size_t)s0 * 64) + lane);
        acc0.x += v0.x; acc0.y += v0.y;
    }
    acc0.x += acc1.x; acc0.y += acc1.y;
    ((__half2*)(ha + (size_t)w * 64))[lane] = __floats2half2_rn(acc0.x, acc0.y);
}

__device__ __forceinline__ void h8_add(float* acc, uint4 v) {
    const __half2* p = (const __half2*)&v;
    #pragma unroll
    for (int i = 0; i < 4; i++) {
        float2 f = __half22float2(p[i]);
        acc[2 * i] += f.x; acc[2 * i + 1] += f.y;
    }
}

// agg256 over fp16 t256 + both head prologues.
// One warp per node; each lane owns 8 contiguous columns (one uint4 of halves).
// Lanes 0-15 cover cols 0-127 (mu head), lanes 16-31 cover cols 128-255 (logvar).
__global__ __launch_bounds__(256) void agg256_heads_kernel(
    const __half* __restrict__ t256, const int* __restrict__ off, const int* __restrict__ deg,
    const int* __restrict__ csr, const float* __restrict__ bm1, const float* __restrict__ bl1,
    __half* __restrict__ hh)
{
    int w = (blockIdx.x * blockDim.x + threadIdx.x) >> 5;
    int lane = threadIdx.x & 31;
    if (w >= N_NODES) return;

    float acc0[8] = {}, acc1[8] = {};
    h8_add(acc0, __ldg((const uint4*)(t256 + (size_t)w * 256) + lane));

    int o = off[w], dg = deg[w];
    int k = 0;
    for (; k + 2 <= dg; k += 2) {
        int s0 = __ldg(csr + o + k);
        int s1 = __ldg(csr + o + k + 1);
        uint4 v0 = __ldg((const uint4*)(t256 + (size_t)s0 * 256) + lane);
        uint4 v1 = __ldg((const uint4*)(t256 + (size_t)s1 * 256) + lane);
        h8_add(acc0, v0);
        h8_add(acc1, v1);
    }
    if (k < dg) {
        int s0 = __ldg(csr + o + k);
        h8_add(acc0, __ldg((const uint4*)(t256 + (size_t)s0 * 256) + lane));
    }
    #pragma unroll
    for (int i = 0; i < 8; i++) acc0[i] += acc1[i];

    const float* bias = (lane < 16) ? (bm1 + lane * 8) : (bl1 + (lane - 16) * 8);
    float4 bv0 = __ldg((const float4*)bias);
    float4 bv1 = __ldg((const float4*)bias + 1);
    float bb[8] = {bv0.x, bv0.y, bv0.z, bv0.w, bv1.x, bv1.y, bv1.z, bv1.w};

    uint4 pk;
    __half2* q = (__half2*)&pk;
    #pragma unroll
    for (int i = 0; i < 4; i++) {
        float v0 = fmaxf(acc0[2 * i]     + bb[2 * i],     0.f);
        float v1 = fmaxf(acc0[2 * i + 1] + bb[2 * i + 1], 0.f);
        q[i] = __floats2half2_rn(v0, v1);
    }
    size_t dst = (lane < 16)
        ? ((size_t)w * 128 + lane * 8)
        : ((size_t)N_NODES * 128 + (size_t)w * 128 + (lane - 16) * 8);
    *(uint4*)(hh + dst) = pk;
}

// ---------------- batched weight convert: fp32 -> fp16 ----------------
struct WSrc { const float2* p[8]; };
__global__ void split_weights_kernel(WSrc ws, __half2* __restrict__ hi) {
    int i = blockIdx.x * blockDim.x + threadIdx.x;
    const int ends[8]   = {16384, 147456, 278528, 409600, 442368, 475136, 483328, 491520};
    const int starts[8] = {0, 16384, 147456, 278528, 409600, 442368, 475136, 483328};
    if (i >= 491520) return;
    int seg = 0;
    #pragma unroll
    for (int s = 0; s < 7; s++) if (i >= ends[s]) seg = s + 1;
    float2 v = ws.p[seg][i - starts[seg]];
    hi[i] = __halves2half2(__float2half(v.x), __float2half(v.y));
}

// ---------------- mma.sync fp16 single-product GEMM (measured-best engine) ----------------
// C[M,Nn] = act(A[M,K] @ W[Nn,K]^T + bias); A, W fp16, fp32 accum.
// CTA tile 128x128, 8 warps of 64x32, K in 64-elem SW128 chunks,
// cp.async double buffer (2 x 32KB smem -> 2 CTA/SM).
// ZSEL: blockIdx.z selects between two (A, W, bias, C) tuples (merged head GEMMs).
#define GT 256
#define SMEM_GEMM 65536
#define BUFB 32768

#define LDSM4(r0, r1, r2, r3, a) \
    asm volatile("ldmatrix.sync.aligned.m8n8.x4.shared.b16 {%0,%1,%2,%3}, [%4];" \
                 : "=r"(r0), "=r"(r1), "=r"(r2), "=r"(r3) : "r"(a))

#define HMMA(c, a0, a1, a2, a3, b0, b1) \
    asm volatile("mma.sync.aligned.m16n8k16.row.col.f32.f16.f16.f32 " \
                 "{%0,%1,%2,%3}, {%4,%5,%6,%7}, {%8,%9}, {%0,%1,%2,%3};" \
                 : "+f"((c)[0]), "+f"((c)[1]), "+f"((c)[2]), "+f"((c)[3]) \
                 : "r"(a0), "r"(a1), "r"(a2), "r"(a3), "r"(b0), "r"(b1))

__device__ __forceinline__ void cp16(uint32_t saddr, const void* gptr, uint32_t sz) {
    asm volatile("cp.async.cg.shared.global [%0], [%1], 16, %2;"
                 :: "r"(saddr), "l"(gptr), "r"(sz) : "memory");
}
#define CP_COMMIT() asm volatile("cp.async.commit_group;" ::: "memory")
#define CP_WAIT(n)  asm volatile("cp.async.wait_group %0;" :: "n"(n) : "memory")

template <int ACT, bool EMITF, bool EMITH, bool HASB, bool ZSEL>
__global__ __launch_bounds__(GT, 2)
void gemm_tc(const __half* __restrict__ A, const __half* __restrict__ A2, int lda,
             const __half* __restrict__ W, const __half* __restrict__ W2,
             const float* __restrict__ bias, const float* __restrict__ bias2,
             float* __restrict__ C, float* __restrict__ C2, int ldc,
             __half* __restrict__ Ch, int ldch,
             int M, int K)
{
    extern __shared__ char smem[];
    const uint32_t sb = smem_u32(smem);

    if (ZSEL && blockIdx.z) { A = A2; W = W2; bias = bias2; C = C2; }

    const int tid = threadIdx.x;
    const int wid = tid >> 5;
    const int lane = tid & 31;
    const int m0 = blockIdx.y * 128;
    const int n0 = blockIdx.x * 128;
    const int wm = (wid & 1) * 64;
    const int wn = (wid >> 1) * 32;

    float acc[4][4][4] = {};

    const int srow = tid >> 3, sg = tid & 7;

    auto stage = [&](int buf, int k0) {
        const uint32_t tb = sb + buf * BUFB;
        #pragma unroll
        for (int t = 0; t < 4; t++) {
            const int row = srow + t * 32;
            const uint32_t so = SW128((uint32_t)(row * 128 + sg * 16));
            const int ar = m0 + row;
            const int ok = (ar < M);
            const size_t ao = (size_t)(ok ? ar : 0) * lda + k0 + sg * 8;
            cp16(tb + 0     + so, A + ao, ok ? 16 : 0);
            const size_t wo = (size_t)(n0 + row) * K + k0 + sg * 8;
            cp16(tb + 16384 + so, W + wo, 16);
        }
        CP_COMMIT();
    };

    const int o = lane >> 3, r = lane & 7;
    int aRow[4];
    #pragma unroll
    for (int i = 0; i < 4; i++) aRow[i] = (wm + 16 * i + (o & 1) * 8 + r) * 128 + (o >> 1) * 16;
    int bRow[2];
    #pragma unroll
    for (int p = 0; p < 2; p++) bRow[p] = (wn + p * 16 + (o >> 1) * 8 + r) * 128 + (o & 1) * 16;

    const int nchunks = K >> 6;
    stage(0, 0);
    for (int c = 0; c < nchunks; c++) {
        if (c + 1 < nchunks) stage((c + 1) & 1, (c + 1) << 6);
        if (c + 1 < nchunks) { CP_WAIT(1); } else { CP_WAIT(0); }
        __syncthreads();

        const uint32_t tb = sb + (c & 1) * BUFB;
        #pragma unroll
        for (int ks = 0; ks < 4; ks++) {
            const int kb = ks * 32;
            uint32_t af[4][4], wf[2][4];
            #pragma unroll
            for (int i = 0; i < 4; i++) {
                const uint32_t ad = SW128((uint32_t)(aRow[i] + kb));
                LDSM4(af[i][0], af[i][1], af[i][2], af[i][3], tb + ad);
            }
            #pragma unroll
            for (int p = 0; p < 2; p++) {
                const uint32_t bd = SW128((uint32_t)(bRow[p] + kb));
                LDSM4(wf[p][0], wf[p][1], wf[p][2], wf[p][3], tb + 16384 + bd);
            }
            #pragma unroll
            for (int i = 0; i < 4; i++) {
                #pragma unroll
                for (int j = 0; j < 4; j++) {
                    HMMA(acc[i][j], af[i][0], af[i][1], af[i][2], af[i][3],
                         wf[j >> 1][(j & 1) * 2], wf[j >> 1][(j & 1) * 2 + 1]);
                }
            }
        }
        __syncthreads();
    }

    const int gid = lane >> 2, tig = lane & 3;
    #pragma unroll
    for (int i = 0; i < 4; i++) {
        #pragma unroll
        for (int h = 0; h < 2; h++) {
            const int row = m0 + wm + 16 * i + 8 * h + gid;
            if (row >= M) continue;
            #pragma unroll
            for (int j = 0; j < 4; j++) {
                const int col = n0 + wn + 8 * j + 2 * tig;
                float v0 = acc[i][j][2 * h], v1 = acc[i][j][2 * h + 1];
                if (HASB) { v0 += __ldg(bias + col); v1 += __ldg(bias + col + 1); }
                if (ACT == 1) { v0 = (v0 > 0.f) ? v0 : 0.1f * v0; v1 = (v1 > 0.f) ? v1 : 0.1f * v1; }
                if (ACT == 2) { v0 = fmaxf(v0, 0.f); v1 = fmaxf(v1, 0.f); }
                if (EMITF) {
                    *(float2*)&C[(size_t)row * ldc + col] = make_float2(v0, v1);
                }
                if (EMITH) {
                    *(__half2*)&Ch[(size_t)row * ldch + col] = __floats2half2_rn(v0, v1);
                }
            }
        }
    }
}

// ---------------- launch ----------------
extern "C" void kernel_launch(void* const* d_in, const int* in_sizes, int n_in,
                              void* d_out, int out_size) {
    const float* x    = (const float*)d_in[0];
    const void*  ei   = d_in[1];
    const float* W_s1 = (const float*)d_in[2];
    const float* b_s1 = (const float*)d_in[3];
    const float* W_s2 = (const float*)d_in[4];
    const float* b_s2 = (const float*)d_in[5];
    const float* W_s3 = (const float*)d_in[6];
    const float* b_s3 = (const float*)d_in[7];
    const float* W_s4 = (const float*)d_in[8];
    const float* b_s4 = (const float*)d_in[9];
    const float* W_m1 = (const float*)d_in[10];
    const float* b_m1 = (const float*)d_in[11];
    const float* W_m2 = (const float*)d_in[12];
    const float* b_m2 = (const float*)d_in[13];
    const float* W_l1 = (const float*)d_in[14];
    const float* b_l1 = (const float*)d_in[15];
    const float* W_l2 = (const float*)d_in[16];
    const float* b_l2 = (const float*)d_in[17];
    float* out = (float*)d_out;

    __half *t256h, *ha, *hb, *wh;
    int *deg, *off, *cursor, *csr, *gbase;
    cudaGetSymbolAddress((void**)&t256h, g_t256h);
    cudaGetSymbolAddress((void**)&ha, g_ha);
    cudaGetSymbolAddress((void**)&hb, g_hb);
    cudaGetSymbolAddress((void**)&wh, g_wh);
    cudaGetSymbolAddress((void**)&deg, g_deg);
    cudaGetSymbolAddress((void**)&off, g_off);
    cudaGetSymbolAddress((void**)&cursor, g_cursor);
    cudaGetSymbolAddress((void**)&csr, g_csr_src);
    cudaGetSymbolAddress((void**)&gbase, g_base);

    static bool init_done = false;
    static cudaStream_t s_side = nullptr;
    static cudaEvent_t ev_fork = nullptr, ev_join = nullptr;
    if (!init_done) {
        cudaFuncSetAttribute(gemm_tc<1, false, true,  true,  false>, cudaFuncAttributeMaxDynamicSharedMemorySize, SMEM_GEMM);
        cudaFuncSetAttribute(gemm_tc<2, false, true,  true,  false>, cudaFuncAttributeMaxDynamicSharedMemorySize, SMEM_GEMM);
        cudaFuncSetAttribute(gemm_tc<0, false, true,  false, false>, cudaFuncAttributeMaxDynamicSharedMemorySize, SMEM_GEMM);
        cudaFuncSetAttribute(gemm_tc<0, true,  false, true,  true >, cudaFuncAttributeMaxDynamicSharedMemorySize, SMEM_GEMM);
        cudaStreamCreateWithFlags(&s_side, cudaStreamNonBlocking);
        cudaEventCreateWithFlags(&ev_fork, cudaEventDisableTiming);
        cudaEventCreateWithFlags(&ev_join, cudaEventDisableTiming);
        init_done = true;
    }

    const int M = N_NODES;
    const dim3 blk(GT);
    const dim3 g512(4, (M + 127) / 128);
    const dim3 g256(2, (M + 127) / 128);
    const dim3 gheads(1, (M + 127) / 128, 2);
    const int SCAN_NB = (N_NODES + SCAN_B - 1) / SCAN_B;

    // ---- fork: weight convert on side stream, overlapped with CSR build ----
    cudaEventRecord(ev_fork, 0);
    cudaStreamWaitEvent(s_side, ev_fork, 0);
    {
        WSrc ws;
        ws.p[0] = (const float2*)W_s1;
        ws.p[1] = (const float2*)W_s2;
        ws.p[2] = (const float2*)W_s3;
        ws.p[3] = (const float2*)W_s4;
        ws.p[4] = (const float2*)W_m1;
        ws.p[5] = (const float2*)W_l1;
        ws.p[6] = (const float2*)W_m2;
        ws.p[7] = (const float2*)W_l2;
        split_weights_kernel<<<(491520 + 255) / 256, 256, 0, s_side>>>(ws, (__half2*)wh);
    }
    cudaEventRecord(ev_join, s_side);

    // ---- main stream: CSR build ----
    detect_idx_kernel<<<1, 32>>>((const unsigned long long*)ei);
    cudaMemsetAsync(deg, 0, N_NODES * sizeof(int), 0);
    hist_kernel<<<(E_EDGES / 2 + 255) / 256, 256>>>(ei, deg);
    scan_fused_kernel<<<SCAN_NB, SCAN_B>>>(deg, off, cursor, gbase);
    csr_fill_kernel<<<(E_EDGES + 255) / 256, 256>>>(ei, cursor, csr);

    // ---- agg0 = (I+A)x -> fp16 ----
    agg64_kernel<<<(N_NODES * 32 + 255) / 256, 256>>>(x, off, deg, csr, ha);

    // ---- join: weights ready before s1 ----
    cudaStreamWaitEvent(0, ev_join, 0);

    // ---- shared MLP, fp16 activations chained through epilogues ----
    gemm_tc<1, false, true, true, false><<<g512, blk, SMEM_GEMM>>>(ha, nullptr, 64,  wh + OFF_S1, nullptr, b_s1, nullptr, nullptr, nullptr, 0, hb, 512, M, 64);
    gemm_tc<1, false, true, true, false><<<g512, blk, SMEM_GEMM>>>(hb, nullptr, 512, wh + OFF_S2, nullptr, b_s2, nullptr, nullptr, nullptr, 0, ha, 512, M, 512);
    gemm_tc<1, false, true, true, false><<<g512, blk, SMEM_GEMM>>>(ha, nullptr, 512, wh + OFF_S3, nullptr, b_s3, nullptr, nullptr, nullptr, 0, hb, 512, M, 512);
    gemm_tc<2, false, true, true, false><<<g512, blk, SMEM_GEMM>>>(hb, nullptr, 512, wh + OFF_S4, nullptr, b_s4, nullptr, nullptr, nullptr, 0, ha, 512, M, 512);

    // ---- t256 = h @ [W_m1; W_l1]^T, emitted directly as fp16 ----
    gemm_tc<0, false, true, false, false><<<g256, blk, SMEM_GEMM>>>(ha, nullptr, 512, wh + OFF_CAT, nullptr, nullptr, nullptr, nullptr, nullptr, 0, t256h, 256, M, 512);

    // ---- agg(256) over fp16 t256 + both head prologues fused ----
    agg256_heads_kernel<<<(N_NODES * 32 + 255) / 256, 256>>>(t256h, off, deg, csr, b_m1, b_l1, hb);

    // ---- both heads in ONE launch (blockIdx.z selects head) ----
    gemm_tc<0, true, false, true, true><<<gheads, blk, SMEM_GEMM>>>(
        hb, hb + (size_t)N_NODES * 128, 128,
        wh + OFF_M2, wh + OFF_L2,
        b_m2, b_l2,
        out, out + (size_t)N_NODES * 128, 128,
        nullptr, 0, M, 128);

    (void)in_sizes; (void)n_in; (void)out_size;
}